// round 11
// baseline (speedup 1.0000x reference)
#include <cuda_runtime.h>
#include <cstdint>

#define Hh 512
#define Ww 512
#define Cc 32
#define Bb 4
#define Ss (Hh*Ww)
#define NG 4               // conv channel groups
#define CPG (Cc/NG)        // 8 channels per group

// Partial per-pixel (off_x, off_y) per channel-group: 4 * 8MB = 32 MB scratch
__device__ float2 g_off_part[NG][Bb * Ss];

typedef unsigned long long ull;

__device__ __forceinline__ ull pack2(float a, float b) {
    ull r; asm("mov.b64 %0, {%1, %2};" : "=l"(r) : "f"(a), "f"(b)); return r;
}
__device__ __forceinline__ void unpack2(ull v, float& a, float& b) {
    asm("mov.b64 {%0, %1}, %2;" : "=f"(a), "=f"(b) : "l"(v));
}
__device__ __forceinline__ ull fma2(ull a, ull b, ull c) {
    ull d; asm("fma.rn.f32x2 %0, %1, %2, %3;" : "=l"(d) : "l"(a), "l"(b), "l"(c)); return d;
}

// ---------------------------------------------------------------------------
// Kernel 1: channel-split barrier-free offset conv (R9 design, unchanged —
// measured ~59us, bandwidth-bound at ~3.5TB/s effective: 134MB x + 32MB
// partials). Warp strip = 128px x 4 rows; per channel stream 6 rows (aligned
// LDG.128 + 2 edge scalars), rotate into 9-tap packed-f32x2 accumulation.
// grid.z = batch*NG: channel loop split over 4 blocks, partials summed by
// the sampler.
// ---------------------------------------------------------------------------
__global__ __launch_bounds__(64) void conv_off_kernel(
    const float* __restrict__ x,
    const float* __restrict__ w_off,
    const float* __restrict__ b_off)
{
    __shared__ ull s_wk[CPG * 9];

    const int tid  = threadIdx.x;
    const int wid  = tid >> 5;
    const int lane = tid & 31;

    const int grp = blockIdx.z & (NG - 1);
    const int bz  = blockIdx.z >> 2;
    const int c0  = grp * CPG;

    for (int i = tid; i < CPG * 9; i += 64)
        s_wk[i] = pack2(__ldg(w_off + c0 * 9 + i),
                        __ldg(w_off + 288 + c0 * 9 + i));
    __syncthreads();

    const int X0   = blockIdx.x * 128;
    const int ytop = blockIdx.y * 8 + wid * 4;
    const int cb   = X0 + 4 * lane;
    const float* xb = x + (size_t)bz * Cc * Ss;

    const ull initp = (grp == 0) ? pack2(__ldg(b_off + 0), __ldg(b_off + 1))
                                 : pack2(0.0f, 0.0f);
    ull acc[4][4];
#pragma unroll
    for (int r = 0; r < 4; r++)
#pragma unroll
        for (int p = 0; p < 4; p++) acc[r][p] = initp;

    const bool has_left  = (cb > 0);
    const bool has_right = (cb + 4 < Ww);

#pragma unroll
    for (int c = 0; c < CPG; c++) {
        const float* xc = xb + (size_t)(c0 + c) * Ss;

        ull wk[9];
#pragma unroll
        for (int k = 0; k < 9; k++) wk[k] = s_wk[c * 9 + k];

#pragma unroll
        for (int j = 0; j < 6; j++) {
            int gy = ytop - 1 + j;
            float v0 = 0.f, v1 = 0.f, v2 = 0.f, v3 = 0.f, v4 = 0.f, v5 = 0.f;
            if ((unsigned)gy < (unsigned)Hh) {
                const float* rp = xc + gy * Ww + cb;
                float4 m = __ldg(reinterpret_cast<const float4*>(rp));
                v1 = m.x; v2 = m.y; v3 = m.z; v4 = m.w;
                if (has_left)  v0 = __ldg(rp - 1);
                if (has_right) v5 = __ldg(rp + 4);
            }
            ull pv[6];
            pv[0] = pack2(v0, v0); pv[1] = pack2(v1, v1);
            pv[2] = pack2(v2, v2); pv[3] = pack2(v3, v3);
            pv[4] = pack2(v4, v4); pv[5] = pack2(v5, v5);

#pragma unroll
            for (int ky = 0; ky < 3; ky++) {
                int r = j - ky;
                if (r >= 0 && r < 4) {
#pragma unroll
                    for (int p = 0; p < 4; p++) {
                        ull a = acc[r][p];
                        a = fma2(pv[p],     wk[ky * 3 + 0], a);
                        a = fma2(pv[p + 1], wk[ky * 3 + 1], a);
                        a = fma2(pv[p + 2], wk[ky * 3 + 2], a);
                        acc[r][p] = a;
                    }
                }
            }
        }
    }

#pragma unroll
    for (int r = 0; r < 4; r++) {
        int y = ytop + r;
        float2* op = g_off_part[grp] + (size_t)bz * Ss + (size_t)y * Ww + cb;
        float ox0, oy0, ox1, oy1, ox2, oy2, ox3, oy3;
        unpack2(acc[r][0], ox0, oy0);
        unpack2(acc[r][1], ox1, oy1);
        unpack2(acc[r][2], ox2, oy2);
        unpack2(acc[r][3], ox3, oy3);
        __stcs(reinterpret_cast<float4*>(op),     make_float4(ox0, oy0, ox1, oy1));
        __stcs(reinterpret_cast<float4*>(op + 2), make_float4(ox2, oy2, ox3, oy3));
    }
}

// ---------------------------------------------------------------------------
// Kernel 2 (R11): SMEM-STAGED gather sampler.
// Evidence: direct-gather sampler is L1-wavefront bound (L1~80% all rounds):
// per-lane row divergence (floor(offy) spans 3-5 rows/warp) splits every
// corner warp-LDG into ~5-7 128B wavefronts. Fix: per block (64x4 px), stage
// a 13-row x 80-col window of 8 channels at a time (33.3KB dynamic smem,
// ~6 blocks/SM) with COALESCED LDGs, then bilinear-gather from smem (LDS has
// no line-splitting penalty). Staged zeros outside the image reproduce the
// zero-padding semantics exactly. Offsets outside the +-4 halo (P~3e-6/px)
// take the global fallback path in the same owning thread.
// ---------------------------------------------------------------------------
#define SW 80                     // staged cols: X0-4 .. X0+75
#define SH 13                     // staged rows: Y0-4 .. Y0+8
#define SCH 8                     // channels per staging chunk
#define SAMP_SMEM (SCH * SH * SW * 4)   // 33280 B

__global__ __launch_bounds__(256) void sample_kernel(
    const float* __restrict__ x,
    float* __restrict__ out)
{
    extern __shared__ float s_x[];   // [SCH][SH][SW]

    const int tid = threadIdx.x;
    const int tx  = tid & 63;
    const int ty  = tid >> 6;
    const int X0  = blockIdx.x * 64;
    const int Y0  = blockIdx.y * 4;
    const int b   = blockIdx.z;

    const int px = X0 + tx;
    const int py = Y0 + ty;
    const int ox = X0 - 4;
    const int oy = Y0 - 4;

    // sum the 4 conv partials -> offset
    const size_t oidx = (size_t)b * Ss + (size_t)py * Ww + px;
    float2 p0 = __ldcs(&g_off_part[0][oidx]);
    float2 p1 = __ldcs(&g_off_part[1][oidx]);
    float2 p2 = __ldcs(&g_off_part[2][oidx]);
    float2 p3 = __ldcs(&g_off_part[3][oidx]);
    float offx = (p0.x + p1.x) + (p2.x + p3.x);
    float offy = (p0.y + p1.y) + (p2.y + p3.y);

    const float ix = (float)px + offx;
    const float iy = (float)py + offy;
    const float x0f = floorf(ix);
    const float y0f = floorf(iy);
    float wx1 = ix - x0f, wx0 = 1.0f - wx1;
    float wy1 = iy - y0f, wy0 = 1.0f - wy1;

    // staged-window coords (integral floats)
    float sxf = x0f - (float)ox;
    float syf = y0f - (float)oy;
    const bool fast = (sxf >= 0.0f) & (sxf <= (float)(SW - 2)) &
                      (syf >= 0.0f) & (syf <= (float)(SH - 2));

    int   s00;
    float w00, w01, w10, w11;
    if (fast) {
        s00 = (int)syf * SW + (int)sxf;
        w00 = wy0 * wx0; w01 = wy0 * wx1;     // no validity terms needed:
        w10 = wy1 * wx0; w11 = wy1 * wx1;     // staged zeros handle padding
    } else {
        s00 = 0;
        w00 = w01 = w10 = w11 = 0.0f;         // fallback overwrites
    }

    const float* xb = x + (size_t)b * Cc * Ss;
    const size_t obase = (size_t)b * Cc * Ss + (size_t)py * Ww + px;

    for (int g = 0; g < Cc / SCH; g++) {
        // ---- stage 8 channels, coalesced, zero-filled outside image ----
#pragma unroll
        for (int c8 = 0; c8 < SCH; c8++) {
            const float* xc = xb + (size_t)(g * SCH + c8) * Ss;
            float* buf = s_x + c8 * (SH * SW);
#pragma unroll
            for (int i = tid; i < SH * SW; i += 256) {
                int r = i / SW;
                int q = i - r * SW;
                int gy = oy + r;
                int gx = ox + q;
                float v = 0.0f;
                if ((unsigned)gy < (unsigned)Hh && (unsigned)gx < (unsigned)Ww)
                    v = __ldg(xc + gy * Ww + gx);
                buf[i] = v;
            }
        }
        __syncthreads();

        // ---- gather from smem ----
#pragma unroll
        for (int c8 = 0; c8 < SCH; c8++) {
            const float* base = s_x + c8 * (SH * SW) + s00;
            float v = w00 * base[0]
                    + w01 * base[1]
                    + w10 * base[SW]
                    + w11 * base[SW + 1];
            __stcs(out + obase + (size_t)(g * SCH + c8) * Ss, v);
        }
        __syncthreads();
    }

    // ---- rare fallback: offset beyond the +-4 halo -> global path ----
    if (!fast) {
        float fx0 = (x0f >= 0.0f && x0f <= 511.0f) ? 1.0f : 0.0f;
        float fx1 = (x0f >= -1.0f && x0f <= 510.0f) ? 1.0f : 0.0f;
        float fy0 = (y0f >= 0.0f && y0f <= 511.0f) ? 1.0f : 0.0f;
        float fy1 = (y0f >= -1.0f && y0f <= 510.0f) ? 1.0f : 0.0f;
        int ix0r = (int)x0f, iy0r = (int)y0f;
        int xi0 = max(0, min(511, ix0r));
        int xi1 = max(0, min(511, ix0r + 1));
        int yi0 = max(0, min(511, iy0r));
        int yi1 = max(0, min(511, iy0r + 1));
        float g00 = wy0 * wx0 * (fy0 * fx0);
        float g01 = wy0 * wx1 * (fy0 * fx1);
        float g10 = wy1 * wx0 * (fy1 * fx0);
        float g11 = wy1 * wx1 * (fy1 * fx1);
        int i00 = yi0 * Ww + xi0, i01 = yi0 * Ww + xi1;
        int i10 = yi1 * Ww + xi0, i11 = yi1 * Ww + xi1;
        for (int c = 0; c < Cc; c++) {
            const float* p = xb + (size_t)c * Ss;
            float v = g00 * __ldg(p + i00) + g01 * __ldg(p + i01)
                    + g10 * __ldg(p + i10) + g11 * __ldg(p + i11);
            out[obase + (size_t)c * Ss] = v;
        }
    }
}

extern "C" void kernel_launch(void* const* d_in, const int* in_sizes, int n_in,
                              void* d_out, int out_size)
{
    const float* x     = (const float*)d_in[0];  // (4, 32, 512, 512)
    const float* w_off = (const float*)d_in[1];  // (18, 32, 3, 3)
    const float* b_off = (const float*)d_in[2];  // (18,)
    float* out = (float*)d_out;                  // (4, 32, 512, 512)

    (void)in_sizes; (void)n_in; (void)out_size;

    dim3 g1(Ww / 128, Hh / 8, Bb * NG);   // (4, 64, 16) blocks x 64 thr
    conv_off_kernel<<<g1, 64>>>(x, w_off, b_off);

    cudaFuncSetAttribute(sample_kernel,
                         cudaFuncAttributeMaxDynamicSharedMemorySize, SAMP_SMEM);
    dim3 g2(Ww / 64, Hh / 4, Bb);         // (8, 128, 4) blocks x 256 thr
    sample_kernel<<<g2, 256, SAMP_SMEM>>>(x, out);
}

// round 12
// speedup vs baseline: 1.5445x; 1.5445x over previous
#include <cuda_runtime.h>
#include <cstdint>

#define Hh 512
#define Ww 512
#define Cc 32
#define Bb 4
#define Ss (Hh*Ww)
#define NG 4               // conv channel groups
#define CPG (Cc/NG)        // 8 channels per group

// Partial per-pixel (off_x, off_y) per channel-group: 4 * 8MB = 32 MB scratch
__device__ float2 g_off_part[NG][Bb * Ss];

typedef unsigned long long ull;

__device__ __forceinline__ ull pack2(float a, float b) {
    ull r; asm("mov.b64 %0, {%1, %2};" : "=l"(r) : "f"(a), "f"(b)); return r;
}
__device__ __forceinline__ void unpack2(ull v, float& a, float& b) {
    asm("mov.b64 {%0, %1}, %2;" : "=f"(a), "=f"(b) : "l"(v));
}
__device__ __forceinline__ ull fma2(ull a, ull b, ull c) {
    ull d; asm("fma.rn.f32x2 %0, %1, %2, %3;" : "=l"(d) : "l"(a), "l"(b), "l"(c)); return d;
}

// Profiling shim: with 3 launches/call ordered (shim, conv, samp), the ncu
// capture slot (launch index 8, inferred from R9's noop capture) lands on the
// CONV kernel — its counters have never been visible. Costs ~1us.
__global__ void profile_shim_kernel() {}

// ---------------------------------------------------------------------------
// Kernel 1: channel-split barrier-free offset conv (R9 design — best
// measured). Only channels 0,1 of the 18 are consumed downstream. Warp strip
// = 128px x 4 rows; per channel stream 6 rows (aligned LDG.128 + 2 edge
// scalars), rotate into the 9-tap packed-f32x2 accumulation. grid.z =
// batch*NG: 32-channel chain split over 4 blocks (8192 warps chip-wide),
// partials summed by the sampler.
// ---------------------------------------------------------------------------
__global__ __launch_bounds__(64) void conv_off_kernel(
    const float* __restrict__ x,
    const float* __restrict__ w_off,
    const float* __restrict__ b_off)
{
    __shared__ ull s_wk[CPG * 9];

    const int tid  = threadIdx.x;
    const int wid  = tid >> 5;
    const int lane = tid & 31;

    const int grp = blockIdx.z & (NG - 1);
    const int bz  = blockIdx.z >> 2;
    const int c0  = grp * CPG;

    for (int i = tid; i < CPG * 9; i += 64)
        s_wk[i] = pack2(__ldg(w_off + c0 * 9 + i),
                        __ldg(w_off + 288 + c0 * 9 + i));
    __syncthreads();

    const int X0   = blockIdx.x * 128;
    const int ytop = blockIdx.y * 8 + wid * 4;
    const int cb   = X0 + 4 * lane;
    const float* xb = x + (size_t)bz * Cc * Ss;

    const ull initp = (grp == 0) ? pack2(__ldg(b_off + 0), __ldg(b_off + 1))
                                 : pack2(0.0f, 0.0f);
    ull acc[4][4];
#pragma unroll
    for (int r = 0; r < 4; r++)
#pragma unroll
        for (int p = 0; p < 4; p++) acc[r][p] = initp;

    const bool has_left  = (cb > 0);
    const bool has_right = (cb + 4 < Ww);

#pragma unroll
    for (int c = 0; c < CPG; c++) {
        const float* xc = xb + (size_t)(c0 + c) * Ss;

        ull wk[9];
#pragma unroll
        for (int k = 0; k < 9; k++) wk[k] = s_wk[c * 9 + k];

#pragma unroll
        for (int j = 0; j < 6; j++) {
            int gy = ytop - 1 + j;
            float v0 = 0.f, v1 = 0.f, v2 = 0.f, v3 = 0.f, v4 = 0.f, v5 = 0.f;
            if ((unsigned)gy < (unsigned)Hh) {
                const float* rp = xc + gy * Ww + cb;
                float4 m = __ldg(reinterpret_cast<const float4*>(rp));
                v1 = m.x; v2 = m.y; v3 = m.z; v4 = m.w;
                if (has_left)  v0 = __ldg(rp - 1);
                if (has_right) v5 = __ldg(rp + 4);
            }
            ull pv[6];
            pv[0] = pack2(v0, v0); pv[1] = pack2(v1, v1);
            pv[2] = pack2(v2, v2); pv[3] = pack2(v3, v3);
            pv[4] = pack2(v4, v4); pv[5] = pack2(v5, v5);

#pragma unroll
            for (int ky = 0; ky < 3; ky++) {
                int r = j - ky;
                if (r >= 0 && r < 4) {
#pragma unroll
                    for (int p = 0; p < 4; p++) {
                        ull a = acc[r][p];
                        a = fma2(pv[p],     wk[ky * 3 + 0], a);
                        a = fma2(pv[p + 1], wk[ky * 3 + 1], a);
                        a = fma2(pv[p + 2], wk[ky * 3 + 2], a);
                        acc[r][p] = a;
                    }
                }
            }
        }
    }

#pragma unroll
    for (int r = 0; r < 4; r++) {
        int y = ytop + r;
        float2* op = g_off_part[grp] + (size_t)bz * Ss + (size_t)y * Ww + cb;
        float ox0, oy0, ox1, oy1, ox2, oy2, ox3, oy3;
        unpack2(acc[r][0], ox0, oy0);
        unpack2(acc[r][1], ox1, oy1);
        unpack2(acc[r][2], ox2, oy2);
        unpack2(acc[r][3], ox3, oy3);
        *reinterpret_cast<float4*>(op)     = make_float4(ox0, oy0, ox1, oy1);
        *reinterpret_cast<float4*>(op + 2) = make_float4(ox2, oy2, ox3, oy3);
    }
}

// ---------------------------------------------------------------------------
// Kernel 2: direct-gather bilinear sampler (proven 66.5us version). Direct L1
// gather beats smem staging for this offset distribution (R11 evidence: 4x
// staging amplification cost 74us). Sums the 4 conv partials, full
// clamp+validity (jnp semantics), coalesced channel loop + streaming stores.
// ---------------------------------------------------------------------------
__global__ __launch_bounds__(256) void sample_kernel(
    const float* __restrict__ x,
    float* __restrict__ out)
{
    const int px = blockIdx.x * 64 + threadIdx.x;
    const int py = blockIdx.y * 4 + threadIdx.y;
    const int b  = blockIdx.z;

    const size_t oidx = (size_t)b * Ss + (size_t)py * Ww + px;
    float2 p0 = __ldg(&g_off_part[0][oidx]);
    float2 p1 = __ldg(&g_off_part[1][oidx]);
    float2 p2 = __ldg(&g_off_part[2][oidx]);
    float2 p3 = __ldg(&g_off_part[3][oidx]);
    float offx = (p0.x + p1.x) + (p2.x + p3.x);
    float offy = (p0.y + p1.y) + (p2.y + p3.y);

    float ix = (float)px + offx;
    float iy = (float)py + offy;

    float x0f = floorf(ix);
    float y0f = floorf(iy);
    float wx1 = ix - x0f, wx0 = 1.0f - wx1;
    float wy1 = iy - y0f, wy0 = 1.0f - wy1;

    float fx0 = (x0f >= 0.0f && x0f <= 511.0f) ? 1.0f : 0.0f;
    float fx1 = (x0f >= -1.0f && x0f <= 510.0f) ? 1.0f : 0.0f;
    float fy0 = (y0f >= 0.0f && y0f <= 511.0f) ? 1.0f : 0.0f;
    float fy1 = (y0f >= -1.0f && y0f <= 510.0f) ? 1.0f : 0.0f;

    int ix0r = (int)x0f;
    int iy0r = (int)y0f;
    int xi0 = max(0, min(511, ix0r));
    int xi1 = max(0, min(511, ix0r + 1));
    int yi0 = max(0, min(511, iy0r));
    int yi1 = max(0, min(511, iy0r + 1));

    float w00 = wy0 * wx0 * (fy0 * fx0);
    float w01 = wy0 * wx1 * (fy0 * fx1);
    float w10 = wy1 * wx0 * (fy1 * fx0);
    float w11 = wy1 * wx1 * (fy1 * fx1);

    const int i00 = yi0 * Ww + xi0;
    const int i01 = yi0 * Ww + xi1;
    const int i10 = yi1 * Ww + xi0;
    const int i11 = yi1 * Ww + xi1;

    const float* xb = x + (size_t)b * Cc * Ss;
    size_t o = (size_t)b * Cc * Ss + (size_t)py * Ww + px;

#pragma unroll 4
    for (int c = 0; c < Cc; c++) {
        const float* p = xb + (size_t)c * Ss;
        float v = w00 * __ldg(p + i00)
                + w01 * __ldg(p + i01)
                + w10 * __ldg(p + i10)
                + w11 * __ldg(p + i11);
        __stcs(out + o + (size_t)c * Ss, v);
    }
}

extern "C" void kernel_launch(void* const* d_in, const int* in_sizes, int n_in,
                              void* d_out, int out_size)
{
    const float* x     = (const float*)d_in[0];  // (4, 32, 512, 512)
    const float* w_off = (const float*)d_in[1];  // (18, 32, 3, 3)
    const float* b_off = (const float*)d_in[2];  // (18,)
    float* out = (float*)d_out;                  // (4, 32, 512, 512)

    (void)in_sizes; (void)n_in; (void)out_size;

    profile_shim_kernel<<<1, 32>>>();   // launch-slot shim: makes ncu capture conv

    dim3 g1(Ww / 128, Hh / 8, Bb * NG);   // (4, 64, 16) blocks x 64 thr
    conv_off_kernel<<<g1, 64>>>(x, w_off, b_off);

    dim3 g2(Ww / 64, Hh / 4, Bb);         // (8, 128, 4) blocks x (64,4) thr
    dim3 t2(64, 4);
    sample_kernel<<<g2, t2>>>(x, out);
}

// round 13
// speedup vs baseline: 1.7961x; 1.1629x over previous
#include <cuda_runtime.h>
#include <cstdint>

#define Hh 512
#define Ww 512
#define Cc 32
#define Bb 4
#define Ss (Hh*Ww)
#define NG 4               // conv channel groups
#define CPG (Cc/NG)        // 8 channels per group

// Partial per-pixel (off_x, off_y) per channel-group: 4 * 8MB = 32 MB scratch
__device__ float2 g_off_part[NG][Bb * Ss];

typedef unsigned long long ull;

__device__ __forceinline__ ull pack2(float a, float b) {
    ull r; asm("mov.b64 %0, {%1, %2};" : "=l"(r) : "f"(a), "f"(b)); return r;
}
__device__ __forceinline__ void unpack2(ull v, float& a, float& b) {
    asm("mov.b64 {%0, %1}, %2;" : "=f"(a), "=f"(b) : "l"(v));
}
__device__ __forceinline__ ull fma2(ull a, ull b, ull c) {
    ull d; asm("fma.rn.f32x2 %0, %1, %2, %3;" : "=l"(d) : "l"(a), "l"(b), "l"(c)); return d;
}

// Profiling shim, now LAST: captured-launch-index analysis across rounds
// (2/call -> pos1; 5/call -> pos2-4; 3/call -> pos0) solves to index 9, so
// with order (conv, samp, shim) ncu captures pos 9 mod 3 = 0 = CONV.
__global__ void profile_shim_kernel() {}

// ---------------------------------------------------------------------------
// Kernel 1 (R13): channel-split conv with 2-CHANNEL ILP INTERLEAVE.
// Model from R8/R9: t = 47us(traffic) + 1.5us * chain_len. NG=4 gives
// chain 8; interleaving two channels per iteration halves chain steps to 4
// and doubles load MLP per step (12 independent LDG.128 rows in flight).
// Warp strip = 128px x 4 rows, barrier-free, packed f32x2 accumulation.
// ---------------------------------------------------------------------------
__global__ __launch_bounds__(64) void conv_off_kernel(
    const float* __restrict__ x,
    const float* __restrict__ w_off,
    const float* __restrict__ b_off)
{
    __shared__ ull s_wk[CPG * 9];

    const int tid  = threadIdx.x;
    const int wid  = tid >> 5;
    const int lane = tid & 31;

    const int grp = blockIdx.z & (NG - 1);
    const int bz  = blockIdx.z >> 2;
    const int c0  = grp * CPG;

    for (int i = tid; i < CPG * 9; i += 64)
        s_wk[i] = pack2(__ldg(w_off + c0 * 9 + i),
                        __ldg(w_off + 288 + c0 * 9 + i));
    __syncthreads();

    const int X0   = blockIdx.x * 128;
    const int ytop = blockIdx.y * 8 + wid * 4;
    const int cb   = X0 + 4 * lane;
    const float* xb = x + (size_t)bz * Cc * Ss;

    const ull initp = (grp == 0) ? pack2(__ldg(b_off + 0), __ldg(b_off + 1))
                                 : pack2(0.0f, 0.0f);
    ull acc[4][4];
#pragma unroll
    for (int r = 0; r < 4; r++)
#pragma unroll
        for (int p = 0; p < 4; p++) acc[r][p] = initp;

    const bool has_left  = (cb > 0);
    const bool has_right = (cb + 4 < Ww);

#pragma unroll
    for (int c = 0; c < CPG; c += 2) {
        const float* xcA = xb + (size_t)(c0 + c) * Ss;
        const float* xcB = xcA + Ss;

        ull wkA[9], wkB[9];
#pragma unroll
        for (int k = 0; k < 9; k++) {
            wkA[k] = s_wk[c * 9 + k];
            wkB[k] = s_wk[(c + 1) * 9 + k];
        }

        // Issue ALL 12 row loads (both channels) before any consumption:
        // 12 independent LDG.128 (+ edge scalars) in flight per step.
        float4 mA[6], mB[6];
        float  lA[6], rA[6], lB[6], rB[6];
#pragma unroll
        for (int j = 0; j < 6; j++) {
            int gy = ytop - 1 + j;
            mA[j] = make_float4(0.f, 0.f, 0.f, 0.f);
            mB[j] = make_float4(0.f, 0.f, 0.f, 0.f);
            lA[j] = rA[j] = lB[j] = rB[j] = 0.f;
            if ((unsigned)gy < (unsigned)Hh) {
                const float* rpA = xcA + gy * Ww + cb;
                const float* rpB = xcB + gy * Ww + cb;
                mA[j] = __ldg(reinterpret_cast<const float4*>(rpA));
                mB[j] = __ldg(reinterpret_cast<const float4*>(rpB));
                if (has_left)  { lA[j] = __ldg(rpA - 1); lB[j] = __ldg(rpB - 1); }
                if (has_right) { rA[j] = __ldg(rpA + 4); rB[j] = __ldg(rpB + 4); }
            }
        }

        // Two independent accumulation chains (A then B per row, interleaved
        // by the compiler's scheduler across the unrolled body).
#pragma unroll
        for (int j = 0; j < 6; j++) {
            ull pvA[6], pvB[6];
            pvA[0] = pack2(lA[j], lA[j]);   pvB[0] = pack2(lB[j], lB[j]);
            pvA[1] = pack2(mA[j].x, mA[j].x); pvB[1] = pack2(mB[j].x, mB[j].x);
            pvA[2] = pack2(mA[j].y, mA[j].y); pvB[2] = pack2(mB[j].y, mB[j].y);
            pvA[3] = pack2(mA[j].z, mA[j].z); pvB[3] = pack2(mB[j].z, mB[j].z);
            pvA[4] = pack2(mA[j].w, mA[j].w); pvB[4] = pack2(mB[j].w, mB[j].w);
            pvA[5] = pack2(rA[j], rA[j]);   pvB[5] = pack2(rB[j], rB[j]);

#pragma unroll
            for (int ky = 0; ky < 3; ky++) {
                int r = j - ky;
                if (r >= 0 && r < 4) {
#pragma unroll
                    for (int p = 0; p < 4; p++) {
                        ull a = acc[r][p];
                        a = fma2(pvA[p],     wkA[ky * 3 + 0], a);
                        a = fma2(pvA[p + 1], wkA[ky * 3 + 1], a);
                        a = fma2(pvA[p + 2], wkA[ky * 3 + 2], a);
                        a = fma2(pvB[p],     wkB[ky * 3 + 0], a);
                        a = fma2(pvB[p + 1], wkB[ky * 3 + 1], a);
                        a = fma2(pvB[p + 2], wkB[ky * 3 + 2], a);
                        acc[r][p] = a;
                    }
                }
            }
        }
    }

#pragma unroll
    for (int r = 0; r < 4; r++) {
        int y = ytop + r;
        float2* op = g_off_part[grp] + (size_t)bz * Ss + (size_t)y * Ww + cb;
        float ox0, oy0, ox1, oy1, ox2, oy2, ox3, oy3;
        unpack2(acc[r][0], ox0, oy0);
        unpack2(acc[r][1], ox1, oy1);
        unpack2(acc[r][2], ox2, oy2);
        unpack2(acc[r][3], ox3, oy3);
        *reinterpret_cast<float4*>(op)     = make_float4(ox0, oy0, ox1, oy1);
        *reinterpret_cast<float4*>(op + 2) = make_float4(ox2, oy2, ox3, oy3);
    }
}

// ---------------------------------------------------------------------------
// Kernel 2: direct-gather bilinear sampler (proven ~66.5us; L1-wavefront
// floor for this structure per R10/R11 evidence). Sums the 4 conv partials,
// full clamp+validity (jnp semantics), coalesced channel loop + streaming
// stores.
// ---------------------------------------------------------------------------
__global__ __launch_bounds__(256) void sample_kernel(
    const float* __restrict__ x,
    float* __restrict__ out)
{
    const int px = blockIdx.x * 64 + threadIdx.x;
    const int py = blockIdx.y * 4 + threadIdx.y;
    const int b  = blockIdx.z;

    const size_t oidx = (size_t)b * Ss + (size_t)py * Ww + px;
    float2 p0 = __ldg(&g_off_part[0][oidx]);
    float2 p1 = __ldg(&g_off_part[1][oidx]);
    float2 p2 = __ldg(&g_off_part[2][oidx]);
    float2 p3 = __ldg(&g_off_part[3][oidx]);
    float offx = (p0.x + p1.x) + (p2.x + p3.x);
    float offy = (p0.y + p1.y) + (p2.y + p3.y);

    float ix = (float)px + offx;
    float iy = (float)py + offy;

    float x0f = floorf(ix);
    float y0f = floorf(iy);
    float wx1 = ix - x0f, wx0 = 1.0f - wx1;
    float wy1 = iy - y0f, wy0 = 1.0f - wy1;

    float fx0 = (x0f >= 0.0f && x0f <= 511.0f) ? 1.0f : 0.0f;
    float fx1 = (x0f >= -1.0f && x0f <= 510.0f) ? 1.0f : 0.0f;
    float fy0 = (y0f >= 0.0f && y0f <= 511.0f) ? 1.0f : 0.0f;
    float fy1 = (y0f >= -1.0f && y0f <= 510.0f) ? 1.0f : 0.0f;

    int ix0r = (int)x0f;
    int iy0r = (int)y0f;
    int xi0 = max(0, min(511, ix0r));
    int xi1 = max(0, min(511, ix0r + 1));
    int yi0 = max(0, min(511, iy0r));
    int yi1 = max(0, min(511, iy0r + 1));

    float w00 = wy0 * wx0 * (fy0 * fx0);
    float w01 = wy0 * wx1 * (fy0 * fx1);
    float w10 = wy1 * wx0 * (fy1 * fx0);
    float w11 = wy1 * wx1 * (fy1 * fx1);

    const int i00 = yi0 * Ww + xi0;
    const int i01 = yi0 * Ww + xi1;
    const int i10 = yi1 * Ww + xi0;
    const int i11 = yi1 * Ww + xi1;

    const float* xb = x + (size_t)b * Cc * Ss;
    size_t o = (size_t)b * Cc * Ss + (size_t)py * Ww + px;

#pragma unroll 4
    for (int c = 0; c < Cc; c++) {
        const float* p = xb + (size_t)c * Ss;
        float v = w00 * __ldg(p + i00)
                + w01 * __ldg(p + i01)
                + w10 * __ldg(p + i10)
                + w11 * __ldg(p + i11);
        __stcs(out + o + (size_t)c * Ss, v);
    }
}

extern "C" void kernel_launch(void* const* d_in, const int* in_sizes, int n_in,
                              void* d_out, int out_size)
{
    const float* x     = (const float*)d_in[0];  // (4, 32, 512, 512)
    const float* w_off = (const float*)d_in[1];  // (18, 32, 3, 3)
    const float* b_off = (const float*)d_in[2];  // (18,)
    float* out = (float*)d_out;                  // (4, 32, 512, 512)

    (void)in_sizes; (void)n_in; (void)out_size;

    dim3 g1(Ww / 128, Hh / 8, Bb * NG);   // (4, 64, 16) blocks x 64 thr
    conv_off_kernel<<<g1, 64>>>(x, w_off, b_off);

    dim3 g2(Ww / 64, Hh / 4, Bb);         // (8, 128, 4) blocks x (64,4) thr
    dim3 t2(64, 4);
    sample_kernel<<<g2, t2>>>(x, out);

    profile_shim_kernel<<<1, 32>>>();     // last: shifts ncu capture onto conv
}